// round 15
// baseline (speedup 1.0000x reference)
#include <cuda_runtime.h>
#include <cuda_bf16.h>
#include <cstdint>
#include <math.h>

#define T_SEQ 2048
#define DM 2048
#define NH 16
#define DH 128
#define SCALE 0.08838834764831845f

__device__ __forceinline__ uint32_t smem_u32(const void* p) {
    uint32_t a;
    asm("{ .reg .u64 t; cvta.to.shared.u64 t, %1; cvt.u32.u64 %0, t; }"
        : "=r"(a) : "l"(p));
    return a;
}

#define LDSM4(r, a) \
    asm volatile("ldmatrix.sync.aligned.m8n8.x4.shared.b16 {%0,%1,%2,%3}, [%4];" \
                 : "=r"((r)[0]), "=r"((r)[1]), "=r"((r)[2]), "=r"((r)[3]) \
                 : "r"(a))

#define MMA16816(d, a, b0, b1) \
    asm volatile( \
        "mma.sync.aligned.m16n8k16.row.col.f32.bf16.bf16.f32 " \
        "{%0,%1,%2,%3},{%4,%5,%6,%7},{%8,%9},{%0,%1,%2,%3};" \
        : "+f"((d)[0]), "+f"((d)[1]), "+f"((d)[2]), "+f"((d)[3]) \
        : "r"((a)[0]), "r"((a)[1]), "r"((a)[2]), "r"((a)[3]), \
          "r"(b0), "r"(b1))

// pack two f32 -> bf16x2 (first arg -> low half)
#define PACKBF(d, lo, hi) \
    asm("cvt.rn.bf16x2.f32 %0, %1, %2;" : "=r"(d) : "f"(hi), "f"(lo))

__device__ __forceinline__ void cp16(uint32_t sa, const void* g) {
    asm volatile("cp.async.cg.shared.global [%0], [%1], 16;"
                 :: "r"(sa), "l"(g));
}
#define CP_COMMIT() asm volatile("cp.async.commit_group;" ::: "memory")
#define CP_WAIT0() asm volatile("cp.async.wait_group 0;" ::: "memory")

// swizzled ldmatrix address inside a 128B-row tile; kc = bf16 col (mult of 8)
__device__ __forceinline__ uint32_t sw_addr(uint32_t base, int row, int kc) {
    return base + (row << 7) + ((((kc >> 3) ^ (row & 7))) << 4);
}

// cp.async a tile of R rows x 64 bf16 (128B rows) with SW128 swizzle
template <int NT>
__device__ __forceinline__ void cp_tile(uint32_t sbase, const char* g,
                                        size_t row_stride, int R, int tid) {
#pragma unroll
    for (int i = tid; i < R * 8; i += NT) {
        int r = i >> 3;
        int cb = (i & 7) << 4;
        uint32_t sw = (uint32_t)(r << 7) + (uint32_t)(cb ^ ((r & 7) << 4));
        cp16(sbase + sw, g + (size_t)r * row_stride + cb);
    }
}

// ===========================================================================
// Scratch (device globals)
// ===========================================================================
__device__ float g_qkv[T_SEQ * 3 * DM];
__device__ __nv_bfloat16 g_hh[T_SEQ * DM], g_hl[T_SEQ * DM];
__device__ __nv_bfloat16 g_wqh[3 * DM * DM], g_wql[3 * DM * DM];
__device__ __nv_bfloat16 g_woh[DM * DM], g_wol[DM * DM];
__device__ __nv_bfloat16 g_ath[T_SEQ * DM], g_atl[T_SEQ * DM];
__device__ __nv_bfloat16 g_qh[NH * T_SEQ * DH], g_ql[NH * T_SEQ * DH];
__device__ __nv_bfloat16 g_kh[NH * T_SEQ * DH], g_kl[NH * T_SEQ * DH];
__device__ __nv_bfloat16 g_vth[NH * DH * T_SEQ], g_vtl[NH * DH * T_SEQ];

// ===========================================================================
// fp32 -> bf16 hi/lo split (weights)
// ===========================================================================
__global__ void split_kernel(const float4* __restrict__ src,
                             __nv_bfloat16* __restrict__ hi,
                             __nv_bfloat16* __restrict__ lo, int n4) {
    int i = blockIdx.x * 256 + threadIdx.x;
    if (i >= n4) return;
    float4 v = src[i];
    float vv[4] = {v.x, v.y, v.z, v.w};
#pragma unroll
    for (int j = 0; j < 4; j++) {
        __nv_bfloat16 h = __float2bfloat16(vv[j]);
        hi[i * 4 + j] = h;
        lo[i * 4 + j] = __float2bfloat16(vv[j] - __bfloat162float(h));
    }
}

// ===========================================================================
// RMSNorm
// ===========================================================================
__global__ void rmsnorm_kernel(const float* __restrict__ x,
                               const float* __restrict__ w,
                               __nv_bfloat16* __restrict__ oh,
                               __nv_bfloat16* __restrict__ ol) {
    int row = blockIdx.x;
    const float* xr = x + row * DM;
    float s = 0.f;
    for (int c = threadIdx.x; c < DM; c += 256) {
        float v = xr[c];
        s += v * v;
    }
    __shared__ float red[256];
    red[threadIdx.x] = s;
    __syncthreads();
    for (int o = 128; o > 0; o >>= 1) {
        if (threadIdx.x < o) red[threadIdx.x] += red[threadIdx.x + o];
        __syncthreads();
    }
    float inv = rsqrtf(red[0] / (float)DM + 1e-6f);
    for (int c = threadIdx.x; c < DM; c += 256) {
        float v = w[c] * xr[c] * inv;
        __nv_bfloat16 h = __float2bfloat16(v);
        oh[row * DM + c] = h;
        ol[row * DM + c] = __float2bfloat16(v - __bfloat162float(h));
    }
}

// ===========================================================================
// HMMA split-bf16 NT GEMM — 128-thread CTA, 128x64 tile, 2 CTAs/SM.
// 2-stage cp.async ring (48KB/stage), prefetch interleaved into k16 slots.
// Stage: Ah(16K) Al(16K) Bh(8K) Bl(8K); stride 49152.
// ===========================================================================
template <int RESID>
__global__ void __launch_bounds__(128, 2)
gemm_mma(const __nv_bfloat16* __restrict__ Ah, const __nv_bfloat16* __restrict__ Al,
         const __nv_bfloat16* __restrict__ Bh, const __nv_bfloat16* __restrict__ Bl,
         float* __restrict__ C, const float* __restrict__ X,
         int M, int N, int K) {
    extern __shared__ char dsm_raw[];
    char* dsm = (char*)(((uintptr_t)dsm_raw + 1023) & ~(uintptr_t)1023);
    uint32_t sa = smem_u32(dsm);

    int tid = threadIdx.x, wid = tid >> 5, lane = tid & 31;
    int n0 = blockIdx.x * 64, m0 = blockIdx.y * 128;
    int wm = (wid >> 1) * 64, wn = (wid & 1) * 32;

    int part = lane >> 3, rw = lane & 7;
    int a_ro = rw + (part & 1) * 8, a_ko = (part >> 1) * 8;
    int b_no = rw + (part >> 1) * 8, b_ko = (part & 1) * 8;

    float acc[4][4][4];
#pragma unroll
    for (int i = 0; i < 4; i++)
#pragma unroll
        for (int j = 0; j < 4; j++)
#pragma unroll
            for (int e = 0; e < 4; e++) acc[i][j][e] = 0.f;

    const int KC = K >> 6;
    size_t rs = (size_t)K * 2;
    const int SSTR = 49152;

    // preload chunk 0 -> stage 0
    cp_tile<128>(sa,         (const char*)(Ah + (size_t)m0 * K), rs, 128, tid);
    cp_tile<128>(sa + 16384, (const char*)(Al + (size_t)m0 * K), rs, 128, tid);
    cp_tile<128>(sa + 32768, (const char*)(Bh + (size_t)n0 * K), rs, 64, tid);
    cp_tile<128>(sa + 40960, (const char*)(Bl + (size_t)n0 * K), rs, 64, tid);
    CP_COMMIT();

    for (int c = 0; c < KC; c++) {
        int st = c & 1;
        CP_WAIT0();
        __syncthreads();

        bool pf = (c + 1 < KC);
        uint32_t psb = sa + (st ^ 1) * SSTR;
        size_t k0p = (size_t)(c + 1) << 6;
        const char* psrc[4] = {
            (const char*)(Ah + (size_t)m0 * K + k0p),
            (const char*)(Al + (size_t)m0 * K + k0p),
            (const char*)(Bh + (size_t)n0 * K + k0p),
            (const char*)(Bl + (size_t)n0 * K + k0p)};
        const uint32_t poff[4] = {0u, 16384u, 32768u, 40960u};
        const int prow[4] = {128, 128, 64, 64};

        uint32_t bAh = sa + st * SSTR;
        uint32_t bAl = bAh + 16384;
        uint32_t bBh = bAh + 32768;
        uint32_t bBl = bAh + 40960;

#pragma unroll
        for (int ko = 0; ko < 64; ko += 16) {
            if (pf) {
                int t = ko >> 4;
                cp_tile<128>(psb + poff[t], psrc[t], rs, prow[t], tid);
            }
            uint32_t ah[4][4], al[4][4], bh[2][4], bl[2][4];
#pragma unroll
            for (int mt = 0; mt < 4; mt++) {
                int row = wm + mt * 16 + a_ro;
                LDSM4(ah[mt], sw_addr(bAh, row, ko + a_ko));
                LDSM4(al[mt], sw_addr(bAl, row, ko + a_ko));
            }
#pragma unroll
            for (int np = 0; np < 2; np++) {
                int nrow = wn + np * 16 + b_no;
                LDSM4(bh[np], sw_addr(bBh, nrow, ko + b_ko));
                LDSM4(bl[np], sw_addr(bBl, nrow, ko + b_ko));
            }
#pragma unroll
            for (int mt = 0; mt < 4; mt++)
#pragma unroll
                for (int nt = 0; nt < 4; nt++) {
                    int np = nt >> 1, half = (nt & 1) * 2;
                    MMA16816(acc[mt][nt], ah[mt], bh[np][half], bh[np][half + 1]);
                    MMA16816(acc[mt][nt], ah[mt], bl[np][half], bl[np][half + 1]);
                    MMA16816(acc[mt][nt], al[mt], bh[np][half], bh[np][half + 1]);
                }
        }
        CP_COMMIT();          // one group per iteration, possibly empty
    }

    int lr = lane >> 2, lc = (lane & 3) * 2;
#pragma unroll
    for (int mt = 0; mt < 4; mt++) {
#pragma unroll
        for (int nt = 0; nt < 4; nt++) {
            int row = m0 + wm + mt * 16 + lr;
            int col = n0 + wn + nt * 8 + lc;
            float2 v0 = make_float2(acc[mt][nt][0], acc[mt][nt][1]);
            float2 v1 = make_float2(acc[mt][nt][2], acc[mt][nt][3]);
            if (RESID) {
                const float2 x0 = *(const float2*)(X + (size_t)row * N + col);
                const float2 x1 = *(const float2*)(X + (size_t)(row + 8) * N + col);
                v0.x += x0.x; v0.y += x0.y;
                v1.x += x1.x; v1.y += x1.y;
            }
            *(float2*)(C + (size_t)row * N + col) = v0;
            *(float2*)(C + (size_t)(row + 8) * N + col) = v1;
        }
    }
}

// ===========================================================================
// Prep: RoPE + scale on q, RoPE on k, hi/lo split head-major; V -> [h][d][t]
// ===========================================================================
__global__ void prep_kernel(const float* __restrict__ qkv,
                            const float* __restrict__ cosb,
                            const float* __restrict__ sinb,
                            __nv_bfloat16* __restrict__ qh, __nv_bfloat16* __restrict__ ql,
                            __nv_bfloat16* __restrict__ kh, __nv_bfloat16* __restrict__ kl,
                            __nv_bfloat16* __restrict__ vth, __nv_bfloat16* __restrict__ vtl) {
    int h = blockIdx.y;
    int t0 = blockIdx.x * 64;
    int tid = threadIdx.x;

    for (int i = tid; i < 64 * 64 * 2; i += 256) {
        int which = i >> 12;
        int rem = i & 4095;
        int tt = rem >> 6, dd = rem & 63;
        int t = t0 + tt;
        const float* p = qkv + (size_t)t * (3 * DM) + which * DM + h * DH;
        float v1 = p[dd], v2 = p[dd + 64];
        float c1 = cosb[t * DH + dd], s1 = sinb[t * DH + dd];
        float c2 = cosb[t * DH + dd + 64], s2 = sinb[t * DH + dd + 64];
        float r1 = v1 * c1 - v2 * s1;
        float r2 = v2 * c2 + v1 * s2;
        if (which == 0) { r1 *= SCALE; r2 *= SCALE; }
        __nv_bfloat16* oh = which ? kh : qh;
        __nv_bfloat16* ol = which ? kl : ql;
        size_t base = ((size_t)h * T_SEQ + t) * DH;
        __nv_bfloat16 h1 = __float2bfloat16(r1);
        oh[base + dd] = h1;
        ol[base + dd] = __float2bfloat16(r1 - __bfloat162float(h1));
        __nv_bfloat16 h2 = __float2bfloat16(r2);
        oh[base + dd + 64] = h2;
        ol[base + dd + 64] = __float2bfloat16(r2 - __bfloat162float(h2));
    }

    __shared__ float vs[64][129];
    for (int i = tid; i < 64 * 128; i += 256) {
        int tt = i >> 7, dd = i & 127;
        vs[tt][dd] = qkv[(size_t)(t0 + tt) * (3 * DM) + 2 * DM + h * DH + dd];
    }
    __syncthreads();
    for (int i = tid; i < 128 * 64; i += 256) {
        int dd = i >> 6, tt = i & 63;
        float v = vs[tt][dd];
        __nv_bfloat16 hh = __float2bfloat16(v);
        size_t o = ((size_t)h * DH + dd) * T_SEQ + t0 + tt;
        vth[o] = hh;
        vtl[o] = __float2bfloat16(v - __bfloat162float(hh));
    }
}

// ===========================================================================
// HMMA flash attention. 1D grid of 256 CTAs, HEAVY-FIRST: qb = 15 - bid/16.
// SMSP-balanced warp->row-block remap rb = {0,2,4,6,7,5,3,1}[wid].
// ===========================================================================
__global__ void __launch_bounds__(256, 1)
flash_mma(const __nv_bfloat16* __restrict__ Qh, const __nv_bfloat16* __restrict__ Ql,
          const __nv_bfloat16* __restrict__ Kh, const __nv_bfloat16* __restrict__ Kl,
          const __nv_bfloat16* __restrict__ Vth, const __nv_bfloat16* __restrict__ Vtl,
          __nv_bfloat16* __restrict__ ath, __nv_bfloat16* __restrict__ atl) {
    extern __shared__ char dsm_raw[];
    char* dsm = (char*)(((uintptr_t)dsm_raw + 1023) & ~(uintptr_t)1023);
    uint32_t sa = smem_u32(dsm);
    const uint32_t sQH = sa, sQL = sa + 32768;
    const uint32_t sST = sa + 65536;

    int tid = threadIdx.x, wid = tid >> 5, lane = tid & 31;
    int bid = blockIdx.x;
    int qb = (T_SEQ / 128) - 1 - (bid >> 4);   // heavy CTAs first
    int h = bid & 15;
    const int tbl[8] = {0, 2, 4, 6, 7, 5, 3, 1};
    int rb = tbl[wid];
    int part = lane >> 3, rw = lane & 7;
    int a_ro = rw + (part & 1) * 8, a_ko = (part >> 1) * 8;
    int b_no = rw + (part >> 1) * 8, b_ko = (part & 1) * 8;
    int lr = lane >> 2, lgrp = lane & 3;
    int qrow0 = qb * 128 + rb * 16;

    const char* Qhh = (const char*)(Qh + ((size_t)h * T_SEQ + qb * 128) * DH);
    const char* Qll = (const char*)(Ql + ((size_t)h * T_SEQ + qb * 128) * DH);

    cp_tile<256>(sQH,         Qhh,       256, 128, tid);
    cp_tile<256>(sQH + 16384, Qhh + 128, 256, 128, tid);
    cp_tile<256>(sQL,         Qll,       256, 128, tid);
    cp_tile<256>(sQL + 16384, Qll + 128, 256, 128, tid);
    CP_COMMIT();

    const int kbmax = 2 * qb + 1;
    {
        uint32_t sb = sST;
        const char* kg = (const char*)(Kh + (size_t)h * T_SEQ * DH);
        const char* lg = (const char*)(Kl + (size_t)h * T_SEQ * DH);
        cp_tile<256>(sb,          kg,       256, 64, tid);
        cp_tile<256>(sb + 8192,   kg + 128, 256, 64, tid);
        cp_tile<256>(sb + 16384,  lg,       256, 64, tid);
        cp_tile<256>(sb + 24576,  lg + 128, 256, 64, tid);
        cp_tile<256>(sb + 32768, (const char*)(Vth + (size_t)h * DH * T_SEQ), T_SEQ * 2, 128, tid);
        cp_tile<256>(sb + 49152, (const char*)(Vtl + (size_t)h * DH * T_SEQ), T_SEQ * 2, 128, tid);
        CP_COMMIT();
    }

    float oc[16][4];
#pragma unroll
    for (int i = 0; i < 16; i++)
#pragma unroll
        for (int e = 0; e < 4; e++) oc[i][e] = 0.f;
    float m0 = -1e30f, m1 = -1e30f, l0 = 0.f, l1 = 0.f;

    for (int kb = 0; kb <= kbmax; kb++) {
        int st = kb & 1;
        CP_WAIT0();
        __syncthreads();
        if (kb + 1 <= kbmax) {
            uint32_t sb = sST + (st ^ 1) * 65536;
            size_t ko = (size_t)(kb + 1) * 64;
            const char* kg = (const char*)(Kh + ((size_t)h * T_SEQ + ko) * DH);
            const char* lg = (const char*)(Kl + ((size_t)h * T_SEQ + ko) * DH);
            cp_tile<256>(sb,         kg,       256, 64, tid);
            cp_tile<256>(sb + 8192,  kg + 128, 256, 64, tid);
            cp_tile<256>(sb + 16384, lg,       256, 64, tid);
            cp_tile<256>(sb + 24576, lg + 128, 256, 64, tid);
            cp_tile<256>(sb + 32768, (const char*)(Vth + (size_t)h * DH * T_SEQ + ko), T_SEQ * 2, 128, tid);
            cp_tile<256>(sb + 49152, (const char*)(Vtl + (size_t)h * DH * T_SEQ + ko), T_SEQ * 2, 128, tid);
            CP_COMMIT();
        }
        if (kb * 64 > qrow0 + 15) continue;  // fully masked for this warp

        uint32_t bKH = sST + st * 65536;
        uint32_t bKL = bKH + 16384;
        uint32_t bVH = bKH + 32768;
        uint32_t bVL = bKH + 49152;

        // ---- S = Q K^T (3-pass), D=128 as 2 chunks x 4 k16 ----
        float sc[8][4];
#pragma unroll
        for (int i = 0; i < 8; i++)
#pragma unroll
            for (int e = 0; e < 4; e++) sc[i][e] = 0.f;
#pragma unroll
        for (int ks = 0; ks < 8; ks++) {
            int ch = ks >> 2;
            int k0 = (ks & 3) * 16;
            uint32_t qH = sQH + ch * 16384, qL = sQL + ch * 16384;
            uint32_t kH = bKH + ch * 8192,  kL = bKL + ch * 8192;
            uint32_t ah[4], al[4], bh[4][4], bl[4][4];
            LDSM4(ah, sw_addr(qH, rb * 16 + a_ro, k0 + a_ko));
            LDSM4(al, sw_addr(qL, rb * 16 + a_ro, k0 + a_ko));
#pragma unroll
            for (int np = 0; np < 4; np++) {
                LDSM4(bh[np], sw_addr(kH, np * 16 + b_no, k0 + b_ko));
                LDSM4(bl[np], sw_addr(kL, np * 16 + b_no, k0 + b_ko));
            }
#pragma unroll
            for (int nt = 0; nt < 8; nt++) {
                int np = nt >> 1, hf = (nt & 1) * 2;
                MMA16816(sc[nt], ah, bh[np][hf], bh[np][hf + 1]);
                MMA16816(sc[nt], ah, bl[np][hf], bl[np][hf + 1]);
                MMA16816(sc[nt], al, bh[np][hf], bh[np][hf + 1]);
            }
        }

        // ---- causal mask (diagonal-straddling blocks only) ----
        if (kb * 64 + 63 > qrow0) {
#pragma unroll
            for (int nt = 0; nt < 8; nt++) {
                int col = kb * 64 + nt * 8 + lgrp * 2;
#pragma unroll
                for (int e = 0; e < 4; e++) {
                    int row = qrow0 + lr + ((e >> 1) << 3);
                    if (col + (e & 1) > row) sc[nt][e] = -1e9f;
                }
            }
        }

        // ---- online softmax ----
        float mx0 = -1e30f, mx1 = -1e30f;
#pragma unroll
        for (int nt = 0; nt < 8; nt++) {
            mx0 = fmaxf(mx0, fmaxf(sc[nt][0], sc[nt][1]));
            mx1 = fmaxf(mx1, fmaxf(sc[nt][2], sc[nt][3]));
        }
        mx0 = fmaxf(mx0, __shfl_xor_sync(0xffffffffu, mx0, 1));
        mx0 = fmaxf(mx0, __shfl_xor_sync(0xffffffffu, mx0, 2));
        mx1 = fmaxf(mx1, __shfl_xor_sync(0xffffffffu, mx1, 1));
        mx1 = fmaxf(mx1, __shfl_xor_sync(0xffffffffu, mx1, 2));
        float mn0 = fmaxf(m0, mx0), mn1 = fmaxf(m1, mx1);
        float al0 = __expf(m0 - mn0), al1 = __expf(m1 - mn1);
        m0 = mn0; m1 = mn1;
        float rs0 = 0.f, rs1 = 0.f;
#pragma unroll
        for (int nt = 0; nt < 8; nt++) {
            sc[nt][0] = __expf(sc[nt][0] - mn0);
            sc[nt][1] = __expf(sc[nt][1] - mn0);
            sc[nt][2] = __expf(sc[nt][2] - mn1);
            sc[nt][3] = __expf(sc[nt][3] - mn1);
            rs0 += sc[nt][0] + sc[nt][1];
            rs1 += sc[nt][2] + sc[nt][3];
        }
        rs0 += __shfl_xor_sync(0xffffffffu, rs0, 1);
        rs0 += __shfl_xor_sync(0xffffffffu, rs0, 2);
        rs1 += __shfl_xor_sync(0xffffffffu, rs1, 1);
        rs1 += __shfl_xor_sync(0xffffffffu, rs1, 2);
        l0 = l0 * al0 + rs0;
        l1 = l1 * al1 + rs1;
#pragma unroll
        for (int nt = 0; nt < 16; nt++) {
            oc[nt][0] *= al0; oc[nt][1] *= al0;
            oc[nt][2] *= al1; oc[nt][3] *= al1;
        }

        // ---- pack P hi/lo ----
        uint32_t ph[8][2], pl[8][2];
#pragma unroll
        for (int nt = 0; nt < 8; nt++) {
            __nv_bfloat16 b0 = __float2bfloat16(sc[nt][0]);
            __nv_bfloat16 b1 = __float2bfloat16(sc[nt][1]);
            __nv_bfloat16 b2 = __float2bfloat16(sc[nt][2]);
            __nv_bfloat16 b3 = __float2bfloat16(sc[nt][3]);
            PACKBF(ph[nt][0], sc[nt][0], sc[nt][1]);
            PACKBF(ph[nt][1], sc[nt][2], sc[nt][3]);
            PACKBF(pl[nt][0], sc[nt][0] - __bfloat162float(b0),
                              sc[nt][1] - __bfloat162float(b1));
            PACKBF(pl[nt][1], sc[nt][2] - __bfloat162float(b2),
                              sc[nt][3] - __bfloat162float(b3));
        }

        // ---- O += P Vt^T (3-pass) ----
#pragma unroll
        for (int ks = 0; ks < 4; ks++) {
            int k0 = ks * 16;
            uint32_t aph[4] = {ph[2 * ks][0], ph[2 * ks][1],
                               ph[2 * ks + 1][0], ph[2 * ks + 1][1]};
            uint32_t apl[4] = {pl[2 * ks][0], pl[2 * ks][1],
                               pl[2 * ks + 1][0], pl[2 * ks + 1][1]};
#pragma unroll
            for (int np = 0; np < 8; np++) {
                uint32_t bvh[4], bvl[4];
                LDSM4(bvh, sw_addr(bVH, np * 16 + b_no, k0 + b_ko));
                LDSM4(bvl, sw_addr(bVL, np * 16 + b_no, k0 + b_ko));
#pragma unroll
                for (int sub = 0; sub < 2; sub++) {
                    int nt = np * 2 + sub, hf = sub * 2;
                    MMA16816(oc[nt], aph, bvh[hf], bvh[hf + 1]);
                    MMA16816(oc[nt], aph, bvl[hf], bvl[hf + 1]);
                    MMA16816(oc[nt], apl, bvh[hf], bvh[hf + 1]);
                }
            }
        }
    }

    // ---- epilogue ----
    float inv0 = 1.f / l0, inv1 = 1.f / l1;
    int t0r = qb * 128 + rb * 16 + lr;
#pragma unroll
    for (int nt = 0; nt < 16; nt++) {
        int dh = nt * 8 + lgrp * 2;
        size_t i0 = (size_t)t0r * DM + h * DH + dh;
        size_t i1 = (size_t)(t0r + 8) * DM + h * DH + dh;
        float v0 = oc[nt][0] * inv0, v1 = oc[nt][1] * inv0;
        float v2 = oc[nt][2] * inv1, v3 = oc[nt][3] * inv1;
        __nv_bfloat16 h0 = __float2bfloat16(v0), h1v = __float2bfloat16(v1);
        __nv_bfloat16 h2 = __float2bfloat16(v2), h3 = __float2bfloat16(v3);
        uint32_t w;
        PACKBF(w, v0, v1); *(uint32_t*)(ath + i0) = w;
        PACKBF(w, v2, v3); *(uint32_t*)(ath + i1) = w;
        PACKBF(w, v0 - __bfloat162float(h0), v1 - __bfloat162float(h1v));
        *(uint32_t*)(atl + i0) = w;
        PACKBF(w, v2 - __bfloat162float(h2), v3 - __bfloat162float(h3));
        *(uint32_t*)(atl + i1) = w;
    }
}

// ===========================================================================
// Launch
// ===========================================================================
extern "C" void kernel_launch(void* const* d_in, const int* in_sizes, int n_in,
                              void* d_out, int out_size) {
    const float* x = (const float*)d_in[0];
    const float* cosb = (const float*)d_in[1];
    const float* sinb = (const float*)d_in[2];
    const float* ln_w = (const float*)d_in[4];
    const float* w_qkv = (const float*)d_in[5];
    const float* w_o = (const float*)d_in[6];
    float* out = (float*)d_out;

    float* g_qkv_p;
    __nv_bfloat16 *g_hh_p, *g_hl_p, *g_wqh_p, *g_wql_p, *g_woh_p, *g_wol_p,
        *g_ath_p, *g_atl_p, *g_qh_p, *g_ql_p, *g_kh_p, *g_kl_p, *g_vth_p, *g_vtl_p;
    cudaGetSymbolAddress((void**)&g_qkv_p, g_qkv);
    cudaGetSymbolAddress((void**)&g_hh_p, g_hh);
    cudaGetSymbolAddress((void**)&g_hl_p, g_hl);
    cudaGetSymbolAddress((void**)&g_wqh_p, g_wqh);
    cudaGetSymbolAddress((void**)&g_wql_p, g_wql);
    cudaGetSymbolAddress((void**)&g_woh_p, g_woh);
    cudaGetSymbolAddress((void**)&g_wol_p, g_wol);
    cudaGetSymbolAddress((void**)&g_ath_p, g_ath);
    cudaGetSymbolAddress((void**)&g_atl_p, g_atl);
    cudaGetSymbolAddress((void**)&g_qh_p, g_qh);
    cudaGetSymbolAddress((void**)&g_ql_p, g_ql);
    cudaGetSymbolAddress((void**)&g_kh_p, g_kh);
    cudaGetSymbolAddress((void**)&g_kl_p, g_kl);
    cudaGetSymbolAddress((void**)&g_vth_p, g_vth);
    cudaGetSymbolAddress((void**)&g_vtl_p, g_vtl);

    // 0. Split weights
    {
        int n4 = (3 * DM * DM) / 4;
        split_kernel<<<(n4 + 255) / 256, 256>>>((const float4*)w_qkv, g_wqh_p,
                                                g_wql_p, n4);
        n4 = (DM * DM) / 4;
        split_kernel<<<(n4 + 255) / 256, 256>>>((const float4*)w_o, g_woh_p,
                                                g_wol_p, n4);
    }

    // 1. RMSNorm
    rmsnorm_kernel<<<T_SEQ, 256>>>(x, ln_w, g_hh_p, g_hl_p);

    const int gemm_smem = 2 * 49152 + 1024;

    // 2. QKV projection: 128x64 tiles, 2 CTAs/SM
    {
        cudaFuncSetAttribute(gemm_mma<0>,
                             cudaFuncAttributeMaxDynamicSharedMemorySize,
                             gemm_smem);
        dim3 grid(3 * DM / 64, T_SEQ / 128);
        gemm_mma<0><<<grid, 128, gemm_smem>>>(g_hh_p, g_hl_p, g_wqh_p, g_wql_p,
                                              g_qkv_p, nullptr, T_SEQ, 3 * DM, DM);
    }

    // 3. Prep: rope + split + V transpose
    {
        dim3 grid(T_SEQ / 64, NH);
        prep_kernel<<<grid, 256>>>(g_qkv_p, cosb, sinb, g_qh_p, g_ql_p,
                                   g_kh_p, g_kl_p, g_vth_p, g_vtl_p);
    }

    // 4. Flash attention (HMMA), heavy-first 1D grid
    {
        const int flash_smem = 3 * 65536 + 1024;
        cudaFuncSetAttribute(flash_mma,
                             cudaFuncAttributeMaxDynamicSharedMemorySize,
                             flash_smem);
        flash_mma<<<(T_SEQ / 128) * NH, 256, flash_smem>>>(
            g_qh_p, g_ql_p, g_kh_p, g_kl_p, g_vth_p, g_vtl_p, g_ath_p, g_atl_p);
    }

    // 5. Output projection + residual
    {
        cudaFuncSetAttribute(gemm_mma<1>,
                             cudaFuncAttributeMaxDynamicSharedMemorySize,
                             gemm_smem);
        dim3 grid(DM / 64, T_SEQ / 128);
        gemm_mma<1><<<grid, 128, gemm_smem>>>(g_ath_p, g_atl_p, g_woh_p, g_wol_p,
                                              out, x, T_SEQ, DM, DM);
    }
}